// round 2
// baseline (speedup 1.0000x reference)
#include <cuda_runtime.h>
#include <cuda_bf16.h>

#define GN 2048   // points per batch
#define GB 16     // batch
#define GC 128    // base channels

// ---------------- scratch (static device globals; no allocation) ----------------
__device__ float g_H0  [GB * GC * GN];          // 16 MB  h after e2
__device__ float g_T   [GB * GN * GC];          // 16 MB  t in (B,N,C) layout
__device__ float g_M   [GB * GN * GC];          // 16 MB  e1 temp (std) / gathered max (NC)
__device__ float g_XCAT[GB * 3 * GC * GN];      // 48 MB
__device__ float g_XF  [GB * 1024 * GN];        // 128 MB
__device__ float g_C1  [GB * 512 * GN];         // 64 MB
__device__ float g_C2  [GB * 256 * GN];         // 32 MB
__device__ int   g_IDX [GB * GN * 16];          // 2 MB
__device__ float g_RMAX[GB * 1024];
__device__ float g_RAVG[GB * 1024];
__device__ float g_B1  [GB * 512];

// ---------------- KNN: per-thread register top-16 ----------------
__global__ void knn_kernel(const float* __restrict__ pts, int* __restrict__ idxout)
{
    __shared__ float4 tile[256];
    int b = blockIdx.x;
    int n = blockIdx.y * 128 + threadIdx.x;
    const float* pb = pts + (long long)b * 6 * GN;
    float px = pb[n], py = pb[GN + n], pz = pb[2 * GN + n];
    float sp = px * px + py * py + pz * pz;

    float best[16];
    int   bidx[16];
#pragma unroll
    for (int i = 0; i < 16; ++i) { best[i] = 3.4e38f; bidx[i] = 0; }

    for (int t0 = 0; t0 < GN; t0 += 256) {
        __syncthreads();
        for (int i = threadIdx.x; i < 256; i += 128) {
            int m = t0 + i;
            float qx = pb[m], qy = pb[GN + m], qz = pb[2 * GN + m];
            tile[i] = make_float4(qx, qy, qz, qx * qx + qy * qy + qz * qz);
        }
        __syncthreads();
        for (int i = 0; i < 256; ++i) {
            float4 q = tile[i];
            float d = sp + q.w - 2.0f * (px * q.x + py * q.y + pz * q.z);
            if (d < best[15]) {
                int cand = t0 + i;
                int pos = 0;
#pragma unroll
                for (int k = 0; k < 16; ++k) pos += (best[k] <= d);
#pragma unroll
                for (int k = 15; k > 0; --k) {
                    if (k > pos) { best[k] = best[k - 1]; bidx[k] = bidx[k - 1]; }
                }
#pragma unroll
                for (int k = 0; k < 16; ++k)
                    if (k == pos) { best[k] = d; bidx[k] = cand; }
            }
        }
    }
    int* op = idxout + ((long long)b * GN + n) * 16;
#pragma unroll
    for (int i = 0; i < 16; ++i) op[i] = bidx[i];
}

// ---------------- e1: Cin=6 pointwise conv ----------------
__global__ void e1_kernel(const float* __restrict__ pts, const float* __restrict__ W,
                          const float* __restrict__ g, const float* __restrict__ bb,
                          float* __restrict__ out)
{
    __shared__ float Wsh[128 * 6];
    __shared__ float gs[128], bs[128];
    int b = blockIdx.x, tid = threadIdx.x;
    int n = blockIdx.y * 256 + tid;
    for (int i = tid; i < 768; i += 256) Wsh[i] = W[i];
    if (tid < 128) { gs[tid] = g[tid]; bs[tid] = bb[tid]; }
    __syncthreads();
    float x[6];
#pragma unroll
    for (int c = 0; c < 6; ++c) x[c] = pts[((long long)b * 6 + c) * GN + n];
    for (int o = 0; o < 128; ++o) {
        float s = 0.f;
#pragma unroll
        for (int c = 0; c < 6; ++c) s += Wsh[o * 6 + c] * x[c];
        s = s * gs[o] + bs[o];
        out[((long long)b * 128 + o) * GN + n] = fmaxf(s, 0.f);
    }
}

// ---------------- generic GEMM: out = act((W@X + pre)*g + post + postB + res) ----------------
// 128x128x16 tiles, 256 threads, 8x8 per thread
__global__ void __launch_bounds__(256) gemm128(
    const float* __restrict__ W, int O, int Cin, int wStride,
    const float* __restrict__ X, long long xB, int xNC,
    float* __restrict__ Yout, long long yB, int yNC,
    const float* __restrict__ pre, const float* __restrict__ gsc,
    const float* __restrict__ post, const float* __restrict__ postB,
    const float* __restrict__ res, long long rB, int act)
{
    __shared__ float Ws[16][129];
    __shared__ float Xs[16][129];
    int b  = blockIdx.z;
    int nb = blockIdx.x * 128;
    int ob = blockIdx.y * 128;
    int tid = threadIdx.x;
    int tx = tid & 15, ty = tid >> 4;
    float acc[8][8] = {};
    const float* Xb = X + (long long)b * xB;

    for (int c0 = 0; c0 < Cin; c0 += 16) {
#pragma unroll
        for (int e = 0; e < 8; ++e) {
            int i = tid + e * 256;
            int c = i & 15, o = i >> 4;
            int og = ob + o;
            Ws[c][o] = (og < O) ? W[(long long)og * wStride + c0 + c] : 0.f;
        }
        if (!xNC) {
#pragma unroll
            for (int e = 0; e < 8; ++e) {
                int i = tid + e * 256;
                int n = i & 127, c = i >> 7;
                Xs[c][n] = Xb[(long long)(c0 + c) * GN + nb + n];
            }
        } else {
#pragma unroll
            for (int e = 0; e < 8; ++e) {
                int i = tid + e * 256;
                int c = i & 15, n = i >> 4;
                Xs[c][n] = Xb[(long long)(nb + n) * Cin + c0 + c];
            }
        }
        __syncthreads();
#pragma unroll
        for (int k = 0; k < 16; ++k) {
            float rw[8], rx[8];
#pragma unroll
            for (int i = 0; i < 8; ++i) rw[i] = Ws[k][ty + 16 * i];
#pragma unroll
            for (int j = 0; j < 8; ++j) rx[j] = Xs[k][tx + 16 * j];
#pragma unroll
            for (int i = 0; i < 8; ++i)
#pragma unroll
                for (int j = 0; j < 8; ++j) acc[i][j] += rw[i] * rx[j];
        }
        __syncthreads();
    }

#pragma unroll
    for (int i = 0; i < 8; ++i) {
        int o = ob + ty + 16 * i;
        if (o >= O) continue;
        float pr = pre  ? pre[o]            : 0.f;
        float gg = gsc  ? gsc[o]            : 1.f;
        float po = post ? post[o]           : 0.f;
        float pb = postB? postB[b * O + o]  : 0.f;
#pragma unroll
        for (int j = 0; j < 8; ++j) {
            int n = nb + tx + 16 * j;
            float v = (acc[i][j] + pr) * gg + po + pb;
            if (res) v += res[(long long)b * rB + (long long)o * GN + n];
            if (act == 1) v = fmaxf(v, 0.f);
            else if (act == 2) v = v > 0.f ? v : 0.2f * v;
            if (!yNC) Yout[(long long)b * yB + (long long)o * GN + n] = v;
            else      Yout[(long long)b * yB + (long long)n * O  + o] = v;
        }
    }
}

// ---------------- gather + max over 16 neighbors (NC layout in & out) ----------------
__global__ void gathermax_kernel(const float* __restrict__ T, const int* __restrict__ IDX,
                                 float* __restrict__ M)
{
    int b = blockIdx.x;
    int warp = threadIdx.x >> 5, lane = threadIdx.x & 31;
    int n = blockIdx.y * 8 + warp;
    const float* tb = T + (long long)b * GN * 128;
    const int* ib = IDX + ((long long)b * GN + n) * 16;
    float4 best = make_float4(-3.4e38f, -3.4e38f, -3.4e38f, -3.4e38f);
#pragma unroll
    for (int k = 0; k < 16; ++k) {
        int j = ib[k];
        float4 v = *((const float4*)(tb + (long long)j * 128) + lane);
        best.x = fmaxf(best.x, v.x); best.y = fmaxf(best.y, v.y);
        best.z = fmaxf(best.z, v.z); best.w = fmaxf(best.w, v.w);
    }
    *((float4*)(M + (long long)b * GN * 128 + (long long)n * 128) + lane) = best;
}

// ---------------- row max+mean over N for XF ----------------
__global__ void reduce_kernel(const float* __restrict__ XF, float* __restrict__ RMAX,
                              float* __restrict__ RAVG)
{
    int r = blockIdx.x * 8 + (threadIdx.x >> 5);
    int lane = threadIdx.x & 31;
    const float4* p = (const float4*)(XF + (long long)r * GN);
    float mx = -3.4e38f, sm = 0.f;
#pragma unroll
    for (int t = 0; t < 16; ++t) {
        float4 v = p[lane + 32 * t];
        mx = fmaxf(mx, fmaxf(fmaxf(v.x, v.y), fmaxf(v.z, v.w)));
        sm += v.x + v.y + v.z + v.w;
    }
#pragma unroll
    for (int off = 16; off; off >>= 1) {
        mx = fmaxf(mx, __shfl_xor_sync(0xffffffffu, mx, off));
        sm += __shfl_xor_sync(0xffffffffu, sm, off);
    }
    if (!lane) { RMAX[r] = mx; RAVG[r] = sm * (1.f / GN); }
}

// ---------------- per-batch bias for c1: Wc1[:,1024:]@[x_max;x_avg;lab] folded ----------------
__global__ void bias1_kernel(const float* __restrict__ Wc1, const float* __restrict__ bc1,
                             const float* __restrict__ gc1, const float* __restrict__ bb1,
                             const float* __restrict__ Wl, const float* __restrict__ gl,
                             const float* __restrict__ bl, const float* __restrict__ label,
                             const float* __restrict__ RMAX, const float* __restrict__ RAVG,
                             float* __restrict__ B1)
{
    int b = blockIdx.x;
    int tid = threadIdx.x, warp = tid >> 5, lane = tid & 31;
    __shared__ float lab[64];
    if (tid < 64) {
        float s = 0.f;
#pragma unroll
        for (int i = 0; i < 16; ++i) s += Wl[tid * 16 + i] * label[b * 16 + i];
        s = s * gl[tid] + bl[tid];
        lab[tid] = s > 0.f ? s : 0.2f * s;
    }
    __syncthreads();
    int o = blockIdx.y * 8 + warp;
    const float* wr = Wc1 + (long long)o * 3136;
    const float* xm = RMAX + b * 1024;
    const float* xa = RAVG + b * 1024;
    float s = 0.f;
    for (int j = lane; j < 1024; j += 32)
        s += wr[1024 + j] * xm[j] + wr[2048 + j] * xa[j];
    for (int j = lane; j < 64; j += 32)
        s += wr[3072 + j] * lab[j];
#pragma unroll
    for (int off = 16; off; off >>= 1) s += __shfl_xor_sync(0xffffffffu, s, off);
    if (!lane) B1[b * 512 + o] = gc1[o] * (s + bc1[o]) + bb1[o];
}

// ---------------- host side ----------------
static float* sym_addr_f(const void* sym) { void* p = nullptr; cudaGetSymbolAddress(&p, sym); return (float*)p; }

static void launch_gemm(const float* W, int O, int Cin, int wStride,
                        const float* X, long long xB, int xNC,
                        float* Y, long long yB, int yNC,
                        const float* pre, const float* g, const float* post, const float* postB,
                        const float* res, long long rB, int act)
{
    dim3 grid(GN / 128, (O + 127) / 128, GB);
    gemm128<<<grid, 256>>>(W, O, Cin, wStride, X, xB, xNC, Y, yB, yNC,
                           pre, g, post, postB, res, rB, act);
}

extern "C" void kernel_launch(void* const* d_in, const int* in_sizes, int n_in,
                              void* d_out, int out_size)
{
    const float* pts   = (const float*)d_in[0];
    const float* label = (const float*)d_in[1];
    const float* We1   = (const float*)d_in[2];
    const float* ge1   = (const float*)d_in[3];
    const float* be1   = (const float*)d_in[4];
    const float* We2   = (const float*)d_in[5];
    const float* ge2   = (const float*)d_in[6];
    const float* be2   = (const float*)d_in[7];
    const float* W1    = (const float*)d_in[8];
    const float* g1    = (const float*)d_in[9];
    const float* b1    = (const float*)d_in[10];
    const float* W2    = (const float*)d_in[11];
    const float* g2    = (const float*)d_in[12];
    const float* b2    = (const float*)d_in[13];
    const float* Wf    = (const float*)d_in[14];
    const float* gf    = (const float*)d_in[15];
    const float* bf    = (const float*)d_in[16];
    const float* Wl    = (const float*)d_in[17];
    const float* gl    = (const float*)d_in[18];
    const float* bl    = (const float*)d_in[19];
    const float* Wc1   = (const float*)d_in[20];
    const float* bc1   = (const float*)d_in[21];
    const float* gc1   = (const float*)d_in[22];
    const float* bb1   = (const float*)d_in[23];
    const float* Wc2   = (const float*)d_in[24];
    const float* bc2   = (const float*)d_in[25];
    const float* gc2   = (const float*)d_in[26];
    const float* bb2   = (const float*)d_in[27];
    const float* Wc3   = (const float*)d_in[28];
    const float* bc3   = (const float*)d_in[29];
    float* out = (float*)d_out;

    float* H0   = sym_addr_f(g_H0);
    float* T    = sym_addr_f(g_T);
    float* M    = sym_addr_f(g_M);
    float* XCAT = sym_addr_f(g_XCAT);
    float* XF   = sym_addr_f(g_XF);
    float* C1   = sym_addr_f(g_C1);
    float* C2   = sym_addr_f(g_C2);
    float* RMAX = sym_addr_f(g_RMAX);
    float* RAVG = sym_addr_f(g_RAVG);
    float* B1   = sym_addr_f(g_B1);
    int* IDX;
    { void* p = nullptr; cudaGetSymbolAddress(&p, g_IDX); IDX = (int*)p; }

    // 1. KNN
    knn_kernel<<<dim3(GB, GN / 128), 128>>>(pts, IDX);

    // 2. embedding
    e1_kernel<<<dim3(GB, GN / 256), 256>>>(pts, We1, ge1, be1, M);
    launch_gemm(We2, 128, 128, 128, M, 128LL * GN, 0, H0, 128LL * GN, 0,
                nullptr, ge2, be2, nullptr, nullptr, 0, 1);

    // 3. three edge blocks
    const float* h = H0;
    long long hB = 128LL * GN;
    for (int i = 0; i < 3; ++i) {
        launch_gemm(W1 + (long long)i * 128 * 128, 128, 128, 128, h, hB, 0,
                    T, 128LL * GN, 1, nullptr, g1 + i * 128, b1 + i * 128,
                    nullptr, nullptr, 0, 1);
        gathermax_kernel<<<dim3(GB, GN / 8), 256>>>(T, IDX, M);
        launch_gemm(W2 + (long long)i * 128 * 128, 128, 128, 128, M, 128LL * GN, 1,
                    XCAT + (long long)i * 128 * GN, 384LL * GN, 0,
                    nullptr, g2 + i * 128, b2 + i * 128, nullptr, h, hB, 1);
        h = XCAT + (long long)i * 128 * GN;
        hB = 384LL * GN;
    }

    // 4. xf = leaky(bn(Wf @ xcat))
    launch_gemm(Wf, 1024, 384, 384, XCAT, 384LL * GN, 0, XF, 1024LL * GN, 0,
                nullptr, gf, bf, nullptr, nullptr, 0, 2);

    // 5. global reductions + per-batch bias for c1
    reduce_kernel<<<GB * 1024 / 8, 256>>>(XF, RMAX, RAVG);
    bias1_kernel<<<dim3(GB, 64), 256>>>(Wc1, bc1, gc1, bb1, Wl, gl, bl, label,
                                        RMAX, RAVG, B1);

    // 6. c1 = relu(gc1 * Wc1[:, :1024]@xf + per-batch bias)
    launch_gemm(Wc1, 512, 1024, 3136, XF, 1024LL * GN, 0, C1, 512LL * GN, 0,
                nullptr, gc1, nullptr, B1, nullptr, 0, 1);

    // 7. c2 = relu((Wc2@c1 + bc2)*gc2 + bb2)
    launch_gemm(Wc2, 256, 512, 512, C1, 512LL * GN, 0, C2, 256LL * GN, 0,
                bc2, gc2, bb2, nullptr, nullptr, 0, 1);

    // 8. out = Wc3@c2 + bc3
    launch_gemm(Wc3, 50, 256, 256, C2, 256LL * GN, 0, out, 50LL * GN, 0,
                bc3, nullptr, nullptr, nullptr, nullptr, 0, 0);
}

// round 3
// speedup vs baseline: 2.1183x; 2.1183x over previous
#include <cuda_runtime.h>
#include <cuda_bf16.h>
#include <cstdint>

#define GN 2048
#define GB 16
#define GC 128
typedef __nv_bfloat16 bf16;

// ---------------- scratch (static device globals; no allocation) ----------------
__device__ __align__(16) bf16 g_E1h[GB*GC*GN], g_E1l[GB*GC*GN];
__device__ __align__(16) bf16 g_Hh [GB*GC*GN], g_Hl [GB*GC*GN];
__device__ __align__(16) bf16 g_Mh [GB*GC*GN], g_Ml [GB*GC*GN];
__device__ __align__(16) float g_T [GB*GN*GC];
__device__ __align__(16) bf16 g_XCh[GB*3*GC*GN], g_XCl[GB*3*GC*GN];
__device__ __align__(16) bf16 g_XFh[(size_t)GB*1024*GN], g_XFl[(size_t)GB*1024*GN];
__device__ __align__(16) bf16 g_C1h[(size_t)GB*512*GN], g_C1l[(size_t)GB*512*GN];
__device__ __align__(16) bf16 g_C2h[(size_t)GB*256*GN], g_C2l[(size_t)GB*256*GN];
__device__ int   g_IDX [GB*GN*16];
__device__ float g_RMAX[GB*1024], g_RAVG[GB*1024], g_B1[GB*512];
// weight hi/lo planes
__device__ __align__(16) bf16 g_We2h[16384],  g_We2l[16384];
__device__ __align__(16) bf16 g_W1h [49152],  g_W1l [49152];
__device__ __align__(16) bf16 g_W2h [49152],  g_W2l [49152];
__device__ __align__(16) bf16 g_Wfh [393216], g_Wfl [393216];
__device__ __align__(16) bf16 g_Wc1h[1605632],g_Wc1l[1605632];
__device__ __align__(16) bf16 g_Wc2h[131072], g_Wc2l[131072];
__device__ __align__(16) bf16 g_Wc3h[12800],  g_Wc3l[12800];

// ---------------- weight fp32 -> hi/lo bf16 planes ----------------
__global__ void convw_kernel(const float* __restrict__ w, bf16* __restrict__ hi,
                             bf16* __restrict__ lo, int n)
{
    int i = blockIdx.x * 256 + threadIdx.x;
    if (i < n) {
        float x = w[i];
        bf16 h = __float2bfloat16(x);
        hi[i] = h;
        lo[i] = __float2bfloat16(x - __bfloat162float(h));
    }
}

// ---------------- KNN: per-thread register top-16 ----------------
__global__ void knn_kernel(const float* __restrict__ pts, int* __restrict__ idxout)
{
    __shared__ float4 tile[256];
    int b = blockIdx.x;
    int n = blockIdx.y * 128 + threadIdx.x;
    const float* pb = pts + (long long)b * 6 * GN;
    float px = pb[n], py = pb[GN + n], pz = pb[2 * GN + n];
    float sp = px * px + py * py + pz * pz;

    float best[16];
    int   bidx[16];
#pragma unroll
    for (int i = 0; i < 16; ++i) { best[i] = 3.4e38f; bidx[i] = 0; }

    for (int t0 = 0; t0 < GN; t0 += 256) {
        __syncthreads();
        for (int i = threadIdx.x; i < 256; i += 128) {
            int m = t0 + i;
            float qx = pb[m], qy = pb[GN + m], qz = pb[2 * GN + m];
            tile[i] = make_float4(qx, qy, qz, qx * qx + qy * qy + qz * qz);
        }
        __syncthreads();
        for (int i = 0; i < 256; ++i) {
            float4 q = tile[i];
            float d = sp + q.w - 2.0f * (px * q.x + py * q.y + pz * q.z);
            if (d < best[15]) {
                int cand = t0 + i;
                int pos = 0;
#pragma unroll
                for (int k = 0; k < 16; ++k) pos += (best[k] <= d);
#pragma unroll
                for (int k = 15; k > 0; --k) {
                    if (k > pos) { best[k] = best[k - 1]; bidx[k] = bidx[k - 1]; }
                }
#pragma unroll
                for (int k = 0; k < 16; ++k)
                    if (k == pos) { best[k] = d; bidx[k] = cand; }
            }
        }
    }
    int* op = idxout + ((long long)b * GN + n) * 16;
#pragma unroll
    for (int i = 0; i < 16; ++i) op[i] = bidx[i];
}

// ---------------- e1: Cin=6 pointwise conv -> bf16 planes (CN) ----------------
__global__ void e1_kernel(const float* __restrict__ pts, const float* __restrict__ W,
                          const float* __restrict__ g, const float* __restrict__ bb,
                          bf16* __restrict__ oh, bf16* __restrict__ ol)
{
    __shared__ float Wsh[128 * 6];
    __shared__ float gs[128], bs[128];
    int b = blockIdx.x, tid = threadIdx.x;
    int n = blockIdx.y * 256 + tid;
    for (int i = tid; i < 768; i += 256) Wsh[i] = W[i];
    if (tid < 128) { gs[tid] = g[tid]; bs[tid] = bb[tid]; }
    __syncthreads();
    float x[6];
#pragma unroll
    for (int c = 0; c < 6; ++c) x[c] = pts[((long long)b * 6 + c) * GN + n];
    for (int o = 0; o < 128; ++o) {
        float s = 0.f;
#pragma unroll
        for (int c = 0; c < 6; ++c) s += Wsh[o * 6 + c] * x[c];
        s = fmaxf(s * gs[o] + bs[o], 0.f);
        bf16 h = __float2bfloat16(s);
        size_t off = ((size_t)b * 128 + o) * GN + n;
        oh[off] = h;
        ol[off] = __float2bfloat16(s - __bfloat162float(h));
    }
}

// ---------------- tensor-core split-bf16 GEMM ----------------
struct GemmArgs {
    const bf16 *Ah, *Al; int O, Cin, wS;
    const bf16 *Bh, *Bl; long long bS;
    float* oF; long long oS; int oNC;
    bf16 *Yh, *Yl; long long yS;
    const float *pre, *g, *post, *postB;
    const bf16 *rH, *rL; long long rS;
    int act;
};

__device__ __forceinline__ uint32_t s2u(const void* p) {
    return (uint32_t)__cvta_generic_to_shared(p);
}
__device__ __forceinline__ void ldm4(uint32_t* r, uint32_t a) {
    asm volatile("ldmatrix.sync.aligned.m8n8.x4.shared.b16 {%0,%1,%2,%3},[%4];\n"
                 : "=r"(r[0]), "=r"(r[1]), "=r"(r[2]), "=r"(r[3]) : "r"(a));
}
__device__ __forceinline__ void ldm4t(uint32_t* r, uint32_t a) {
    asm volatile("ldmatrix.sync.aligned.m8n8.x4.trans.shared.b16 {%0,%1,%2,%3},[%4];\n"
                 : "=r"(r[0]), "=r"(r[1]), "=r"(r[2]), "=r"(r[3]) : "r"(a));
}
__device__ __forceinline__ void mma16816(float* d, const uint32_t* A, uint32_t b0, uint32_t b1) {
    asm volatile(
        "mma.sync.aligned.m16n8k16.row.col.f32.bf16.bf16.f32 "
        "{%0,%1,%2,%3},{%4,%5,%6,%7},{%8,%9},{%0,%1,%2,%3};\n"
        : "+f"(d[0]), "+f"(d[1]), "+f"(d[2]), "+f"(d[3])
        : "r"(A[0]), "r"(A[1]), "r"(A[2]), "r"(A[3]), "r"(b0), "r"(b1));
}

// smem: A [buf][plane][128][40]bf16 (row 80B)  = 40960B
//       B [buf][plane][32][136]bf16 (row 272B) = 34816B  -> 75776B total
#define SMEM_GEMM 75776
#define SMEM_BOFF 40960

__global__ void __launch_bounds__(256, 2) gemm_mma(GemmArgs A_)
{
    extern __shared__ char sm[];
    const int tid = threadIdx.x, lane = tid & 31, wid = tid >> 5;
    const int wm = wid & 1, wn = wid >> 1;
    const int b = blockIdx.z, n0 = blockIdx.x * 128, o0 = blockIdx.y * 128;
    const bf16* Bhp = A_.Bh + (long long)b * A_.bS + n0;
    const bf16* Blp = A_.Bl + (long long)b * A_.bS + n0;

    float acc[4][4][4];
#pragma unroll
    for (int i = 0; i < 4; ++i)
#pragma unroll
        for (int j = 0; j < 4; ++j)
#pragma unroll
            for (int k = 0; k < 4; ++k) acc[i][j][k] = 0.f;

    const int nch = A_.Cin >> 5;

    // --- async tile loaders ---
    auto issue = [&](int buf, int c0) {
#pragma unroll
        for (int i = 0; i < 4; ++i) {               // A: 1024 16B chunks
            int idx = tid + i * 256;
            int kc = idx & 3, row = (idx >> 2) & 127, p = idx >> 9;
            int o = o0 + row;
            const bf16* base = p ? A_.Al : A_.Ah;
            bool ok = (o < A_.O);
            const bf16* src = ok ? base + (long long)o * A_.wS + c0 + kc * 8 : base;
            uint32_t dst = s2u(sm + (((buf * 2 + p) * 128 + row) * 80 + kc * 16));
            int sz = ok ? 16 : 0;
            asm volatile("cp.async.ca.shared.global [%0],[%1],16,%2;\n"
                         :: "r"(dst), "l"(src), "r"(sz));
        }
#pragma unroll
        for (int i = 0; i < 4; ++i) {               // B: 1024 16B chunks
            int idx = tid + i * 256;
            int kc = idx & 15, row = (idx >> 4) & 31, p = idx >> 9;
            const bf16* src = (p ? Blp : Bhp) + (long long)(c0 + row) * GN + kc * 8;
            uint32_t dst = s2u(sm + SMEM_BOFF + (((buf * 2 + p) * 32 + row) * 272 + kc * 16));
            asm volatile("cp.async.ca.shared.global [%0],[%1],16,16;\n"
                         :: "r"(dst), "l"(src));
        }
        asm volatile("cp.async.commit_group;\n");
    };

    const int g8 = lane >> 3, r8 = lane & 7;
    const int rowIn16 = r8 + (g8 & 1) * 8;    // row within 16-tile for this lane's ldmatrix addr
    const int colOff  = (g8 >> 1) * 8;        // k/n half offset

    auto compute = [&](int buf) {
#pragma unroll
        for (int ks = 0; ks < 2; ++ks) {
            uint32_t ah[4][4], al[4][4];
#pragma unroll
            for (int mt = 0; mt < 4; ++mt) {
                int row = wm * 64 + mt * 16 + rowIn16;
                uint32_t aH = s2u(sm + ((buf * 2 + 0) * 128 + row) * 80 + (ks * 16 + colOff) * 2);
                uint32_t aL = s2u(sm + ((buf * 2 + 1) * 128 + row) * 80 + (ks * 16 + colOff) * 2);
                ldm4(ah[mt], aH);
                ldm4(al[mt], aL);
            }
#pragma unroll
            for (int nt2 = 0; nt2 < 2; ++nt2) {
                int brow = ks * 16 + rowIn16;
                int bcol = wn * 32 + nt2 * 16 + colOff;
                uint32_t bH = s2u(sm + SMEM_BOFF + ((buf * 2 + 0) * 32 + brow) * 272 + bcol * 2);
                uint32_t bL = s2u(sm + SMEM_BOFF + ((buf * 2 + 1) * 32 + brow) * 272 + bcol * 2);
                uint32_t bh[4], bl[4];
                ldm4t(bh, bH);
                ldm4t(bl, bL);
#pragma unroll
                for (int mt = 0; mt < 4; ++mt) {
                    mma16816(acc[mt][nt2 * 2],     ah[mt], bh[0], bh[1]);
                    mma16816(acc[mt][nt2 * 2 + 1], ah[mt], bh[2], bh[3]);
                    mma16816(acc[mt][nt2 * 2],     ah[mt], bl[0], bl[1]);
                    mma16816(acc[mt][nt2 * 2 + 1], ah[mt], bl[2], bl[3]);
                    mma16816(acc[mt][nt2 * 2],     al[mt], bh[0], bh[1]);
                    mma16816(acc[mt][nt2 * 2 + 1], al[mt], bh[2], bh[3]);
                }
            }
        }
    };

    issue(0, 0);
    for (int c = 0; c < nch; ++c) {
        int buf = c & 1;
        if (c + 1 < nch) {
            issue(buf ^ 1, (c + 1) * 32);
            asm volatile("cp.async.wait_group 1;\n");
        } else {
            asm volatile("cp.async.wait_group 0;\n");
        }
        __syncthreads();
        compute(buf);
        __syncthreads();
    }

    // --- epilogue ---
    const int q = lane >> 2, tcol = (lane & 3) * 2;
#pragma unroll
    for (int mt = 0; mt < 4; ++mt) {
        int oBase = o0 + wm * 64 + mt * 16;
#pragma unroll
        for (int hh = 0; hh < 2; ++hh) {
            int o = oBase + q + hh * 8;
            if (o >= A_.O) continue;
            float pr = A_.pre ? A_.pre[o] : 0.f;
            float gg = A_.g ? A_.g[o] : 1.f;
            float po = A_.post ? A_.post[o] : 0.f;
            if (A_.postB) po += A_.postB[b * A_.O + o];
            long long rowOff = (long long)o * GN;
#pragma unroll
            for (int nt = 0; nt < 4; ++nt) {
                int n = n0 + wn * 32 + nt * 8 + tcol;
                float v0 = (acc[mt][nt][hh * 2 + 0] + pr) * gg + po;
                float v1 = (acc[mt][nt][hh * 2 + 1] + pr) * gg + po;
                if (A_.rH) {
                    long long rb = (long long)b * A_.rS + rowOff + n;
                    v0 += __bfloat162float(A_.rH[rb]) + __bfloat162float(A_.rL[rb]);
                    v1 += __bfloat162float(A_.rH[rb + 1]) + __bfloat162float(A_.rL[rb + 1]);
                }
                if (A_.act == 1) { v0 = fmaxf(v0, 0.f); v1 = fmaxf(v1, 0.f); }
                else if (A_.act == 2) { v0 = v0 > 0.f ? v0 : 0.2f * v0; v1 = v1 > 0.f ? v1 : 0.2f * v1; }
                if (A_.Yh) {
                    long long yb = (long long)b * A_.yS + rowOff + n;
                    bf16 h0 = __float2bfloat16(v0), h1 = __float2bfloat16(v1);
                    __nv_bfloat162 hp; hp.x = h0; hp.y = h1;
                    *(__nv_bfloat162*)(A_.Yh + yb) = hp;
                    __nv_bfloat162 lp;
                    lp.x = __float2bfloat16(v0 - __bfloat162float(h0));
                    lp.y = __float2bfloat16(v1 - __bfloat162float(h1));
                    *(__nv_bfloat162*)(A_.Yl + yb) = lp;
                }
                if (A_.oF) {
                    if (A_.oNC) {
                        float* pp = A_.oF + (long long)b * A_.oS;
                        pp[(long long)n * A_.O + o] = v0;
                        pp[(long long)(n + 1) * A_.O + o] = v1;
                    } else {
                        *(float2*)(A_.oF + (long long)b * A_.oS + rowOff + n) = make_float2(v0, v1);
                    }
                }
            }
        }
    }
}

// ---------------- gather + max (T fp32 NC in -> M bf16 planes CN out) ----------------
__global__ void gathermax_kernel(const float* __restrict__ T, const int* __restrict__ IDX,
                                 bf16* __restrict__ Mh, bf16* __restrict__ Ml)
{
    __shared__ float s[8][128];
    int b = blockIdx.x;
    int w = threadIdx.x >> 5, l = threadIdx.x & 31;
    int n0 = blockIdx.y * 8;
    int n = n0 + w;
    const float* tb = T + (size_t)b * GN * 128;
    const int* ib = IDX + ((size_t)b * GN + n) * 16;
    float4 best = make_float4(-3.4e38f, -3.4e38f, -3.4e38f, -3.4e38f);
#pragma unroll
    for (int k = 0; k < 16; ++k) {
        int j = ib[k];
        float4 v = *((const float4*)(tb + (size_t)j * 128) + l);
        best.x = fmaxf(best.x, v.x); best.y = fmaxf(best.y, v.y);
        best.z = fmaxf(best.z, v.z); best.w = fmaxf(best.w, v.w);
    }
    ((float4*)s[w])[l] = best;
    __syncthreads();
    int c = threadIdx.x;
    if (c < 128) {
        __align__(16) bf16 hi8[8];
        __align__(16) bf16 lo8[8];
#pragma unroll
        for (int j = 0; j < 8; ++j) {
            float v = s[j][c];
            bf16 h = __float2bfloat16(v);
            hi8[j] = h;
            lo8[j] = __float2bfloat16(v - __bfloat162float(h));
        }
        size_t off = ((size_t)b * 128 + c) * GN + n0;
        *(uint4*)(Mh + off) = *(uint4*)hi8;
        *(uint4*)(Ml + off) = *(uint4*)lo8;
    }
}

// ---------------- row max+mean over N for XF (reconstruct hi+lo) ----------------
__global__ void reduce_kernel(const bf16* __restrict__ XFh, const bf16* __restrict__ XFl,
                              float* __restrict__ RMAX, float* __restrict__ RAVG)
{
    int r = blockIdx.x * 8 + (threadIdx.x >> 5);
    int l = threadIdx.x & 31;
    const uint4* ph = (const uint4*)(XFh + (size_t)r * GN);
    const uint4* pl = (const uint4*)(XFl + (size_t)r * GN);
    float mx = -3.4e38f, sm = 0.f;
#pragma unroll
    for (int t = 0; t < 8; ++t) {
        uint4 H = ph[l + 32 * t], L = pl[l + 32 * t];
        const uint32_t* hw = (const uint32_t*)&H;
        const uint32_t* lw = (const uint32_t*)&L;
#pragma unroll
        for (int i = 0; i < 4; ++i) {
            float2 fh = __bfloat1622float2(*(const __nv_bfloat162*)&hw[i]);
            float2 fl = __bfloat1622float2(*(const __nv_bfloat162*)&lw[i]);
            float v0 = fh.x + fl.x, v1 = fh.y + fl.y;
            mx = fmaxf(mx, fmaxf(v0, v1));
            sm += v0 + v1;
        }
    }
#pragma unroll
    for (int off = 16; off; off >>= 1) {
        mx = fmaxf(mx, __shfl_xor_sync(0xffffffffu, mx, off));
        sm += __shfl_xor_sync(0xffffffffu, sm, off);
    }
    if (!l) { RMAX[r] = mx; RAVG[r] = sm * (1.f / GN); }
}

// ---------------- per-batch bias for c1 ----------------
__global__ void bias1_kernel(const float* __restrict__ Wc1, const float* __restrict__ bc1,
                             const float* __restrict__ gc1, const float* __restrict__ bb1,
                             const float* __restrict__ Wl, const float* __restrict__ gl,
                             const float* __restrict__ bl, const float* __restrict__ label,
                             const float* __restrict__ RMAX, const float* __restrict__ RAVG,
                             float* __restrict__ B1)
{
    int b = blockIdx.x;
    int tid = threadIdx.x, warp = tid >> 5, lane = tid & 31;
    __shared__ float lab[64];
    if (tid < 64) {
        float s = 0.f;
#pragma unroll
        for (int i = 0; i < 16; ++i) s += Wl[tid * 16 + i] * label[b * 16 + i];
        s = s * gl[tid] + bl[tid];
        lab[tid] = s > 0.f ? s : 0.2f * s;
    }
    __syncthreads();
    int o = blockIdx.y * 8 + warp;
    const float* wr = Wc1 + (long long)o * 3136;
    const float* xm = RMAX + b * 1024;
    const float* xa = RAVG + b * 1024;
    float s = 0.f;
    for (int j = lane; j < 1024; j += 32)
        s += wr[1024 + j] * xm[j] + wr[2048 + j] * xa[j];
    for (int j = lane; j < 64; j += 32)
        s += wr[3072 + j] * lab[j];
#pragma unroll
    for (int off = 16; off; off >>= 1) s += __shfl_xor_sync(0xffffffffu, s, off);
    if (!lane) B1[b * 512 + o] = gc1[o] * (s + bc1[o]) + bb1[o];
}

// ---------------- host side ----------------
template <class T>
static T* symp(const void* s) { void* p = nullptr; cudaGetSymbolAddress(&p, s); return (T*)p; }

static void run_gemm(const bf16* Ah, const bf16* Al, int O, int Cin, int wS,
                     const bf16* Bh, const bf16* Bl, long long bS,
                     float* oF, long long oS, int oNC,
                     bf16* Yh, bf16* Yl, long long yS,
                     const float* pre, const float* g, const float* post, const float* postB,
                     const bf16* rH, const bf16* rL, long long rS, int act)
{
    GemmArgs a;
    a.Ah = Ah; a.Al = Al; a.O = O; a.Cin = Cin; a.wS = wS;
    a.Bh = Bh; a.Bl = Bl; a.bS = bS;
    a.oF = oF; a.oS = oS; a.oNC = oNC;
    a.Yh = Yh; a.Yl = Yl; a.yS = yS;
    a.pre = pre; a.g = g; a.post = post; a.postB = postB;
    a.rH = rH; a.rL = rL; a.rS = rS; a.act = act;
    dim3 grid(GN / 128, (O + 127) / 128, GB);
    gemm_mma<<<grid, 256, SMEM_GEMM>>>(a);
}

static void conv_w(const float* w, bf16* hi, bf16* lo, int n)
{
    convw_kernel<<<(n + 255) / 256, 256>>>(w, hi, lo, n);
}

extern "C" void kernel_launch(void* const* d_in, const int* in_sizes, int n_in,
                              void* d_out, int out_size)
{
    const float* pts   = (const float*)d_in[0];
    const float* label = (const float*)d_in[1];
    const float* We1   = (const float*)d_in[2];
    const float* ge1   = (const float*)d_in[3];
    const float* be1   = (const float*)d_in[4];
    const float* We2   = (const float*)d_in[5];
    const float* ge2   = (const float*)d_in[6];
    const float* be2   = (const float*)d_in[7];
    const float* W1    = (const float*)d_in[8];
    const float* g1    = (const float*)d_in[9];
    const float* b1    = (const float*)d_in[10];
    const float* W2    = (const float*)d_in[11];
    const float* g2    = (const float*)d_in[12];
    const float* b2    = (const float*)d_in[13];
    const float* Wf    = (const float*)d_in[14];
    const float* gf    = (const float*)d_in[15];
    const float* bf_   = (const float*)d_in[16];
    const float* Wl    = (const float*)d_in[17];
    const float* gl    = (const float*)d_in[18];
    const float* bl    = (const float*)d_in[19];
    const float* Wc1   = (const float*)d_in[20];
    const float* bc1   = (const float*)d_in[21];
    const float* gc1   = (const float*)d_in[22];
    const float* bb1   = (const float*)d_in[23];
    const float* Wc2   = (const float*)d_in[24];
    const float* bc2   = (const float*)d_in[25];
    const float* gc2   = (const float*)d_in[26];
    const float* bb2   = (const float*)d_in[27];
    const float* Wc3   = (const float*)d_in[28];
    const float* bc3   = (const float*)d_in[29];
    float* out = (float*)d_out;

    cudaFuncSetAttribute(gemm_mma, cudaFuncAttributeMaxDynamicSharedMemorySize, SMEM_GEMM);

    bf16 *E1h = symp<bf16>(g_E1h), *E1l = symp<bf16>(g_E1l);
    bf16 *Hh  = symp<bf16>(g_Hh),  *Hl  = symp<bf16>(g_Hl);
    bf16 *Mh  = symp<bf16>(g_Mh),  *Ml  = symp<bf16>(g_Ml);
    bf16 *XCh = symp<bf16>(g_XCh), *XCl = symp<bf16>(g_XCl);
    bf16 *XFh = symp<bf16>(g_XFh), *XFl = symp<bf16>(g_XFl);
    bf16 *C1h = symp<bf16>(g_C1h), *C1l = symp<bf16>(g_C1l);
    bf16 *C2h = symp<bf16>(g_C2h), *C2l = symp<bf16>(g_C2l);
    float* T    = symp<float>(g_T);
    float* RMAX = symp<float>(g_RMAX);
    float* RAVG = symp<float>(g_RAVG);
    float* B1   = symp<float>(g_B1);
    int*   IDX  = symp<int>(g_IDX);
    bf16 *We2h = symp<bf16>(g_We2h), *We2l = symp<bf16>(g_We2l);
    bf16 *W1h  = symp<bf16>(g_W1h),  *W1l  = symp<bf16>(g_W1l);
    bf16 *W2h  = symp<bf16>(g_W2h),  *W2l  = symp<bf16>(g_W2l);
    bf16 *Wfh  = symp<bf16>(g_Wfh),  *Wfl  = symp<bf16>(g_Wfl);
    bf16 *Wc1h = symp<bf16>(g_Wc1h), *Wc1l = symp<bf16>(g_Wc1l);
    bf16 *Wc2h = symp<bf16>(g_Wc2h), *Wc2l = symp<bf16>(g_Wc2l);
    bf16 *Wc3h = symp<bf16>(g_Wc3h), *Wc3l = symp<bf16>(g_Wc3l);

    // weight conversion
    conv_w(We2, We2h, We2l, 16384);
    conv_w(W1,  W1h,  W1l,  49152);
    conv_w(W2,  W2h,  W2l,  49152);
    conv_w(Wf,  Wfh,  Wfl,  393216);
    conv_w(Wc1, Wc1h, Wc1l, 1605632);
    conv_w(Wc2, Wc2h, Wc2l, 131072);
    conv_w(Wc3, Wc3h, Wc3l, 12800);

    // 1. KNN
    knn_kernel<<<dim3(GB, GN / 128), 128>>>(pts, IDX);

    // 2. embedding
    e1_kernel<<<dim3(GB, GN / 256), 256>>>(pts, We1, ge1, be1, E1h, E1l);
    run_gemm(We2h, We2l, 128, 128, 128, E1h, E1l, 128LL * GN,
             nullptr, 0, 0, Hh, Hl, 128LL * GN,
             nullptr, ge2, be2, nullptr, nullptr, nullptr, 0, 1);

    // 3. three edge blocks
    const bf16 *hH = Hh, *hL = Hl;
    long long hB = 128LL * GN;
    for (int i = 0; i < 3; ++i) {
        // t = relu(bn(W1 h))   -> fp32 NC layout for gather
        run_gemm(W1h + (long long)i * 16384, W1l + (long long)i * 16384, 128, 128, 128,
                 hH, hL, hB,
                 T, 128LL * GN, 1, nullptr, nullptr, 0,
                 nullptr, g1 + i * 128, b1 + i * 128, nullptr, nullptr, nullptr, 0, 1);
        gathermax_kernel<<<dim3(GB, GN / 8), 256>>>(T, IDX, Mh, Ml);
        // h = relu(bn(W2 m) + h)  -> XCAT segment planes
        run_gemm(W2h + (long long)i * 16384, W2l + (long long)i * 16384, 128, 128, 128,
                 Mh, Ml, 128LL * GN,
                 nullptr, 0, 0,
                 XCh + (long long)i * 128 * GN, XCl + (long long)i * 128 * GN, 384LL * GN,
                 nullptr, g2 + i * 128, b2 + i * 128, nullptr, hH, hL, hB, 1);
        hH = XCh + (long long)i * 128 * GN;
        hL = XCl + (long long)i * 128 * GN;
        hB = 384LL * GN;
    }

    // 4. xf = leaky(bn(Wf @ xcat))
    run_gemm(Wfh, Wfl, 1024, 384, 384, XCh, XCl, 384LL * GN,
             nullptr, 0, 0, XFh, XFl, 1024LL * GN,
             nullptr, gf, bf_, nullptr, nullptr, nullptr, 0, 2);

    // 5. global reductions + per-batch bias for c1
    reduce_kernel<<<GB * 1024 / 8, 256>>>(XFh, XFl, RMAX, RAVG);
    bias1_kernel<<<dim3(GB, 64), 256>>>(Wc1, bc1, gc1, bb1, Wl, gl, bl, label,
                                        RMAX, RAVG, B1);

    // 6. c1 = relu(gc1 * Wc1[:, :1024]@xf + per-batch bias)
    run_gemm(Wc1h, Wc1l, 512, 1024, 3136, XFh, XFl, 1024LL * GN,
             nullptr, 0, 0, C1h, C1l, 512LL * GN,
             nullptr, gc1, nullptr, B1, nullptr, nullptr, 0, 1);

    // 7. c2 = relu((Wc2@c1 + bc2)*gc2 + bb2)
    run_gemm(Wc2h, Wc2l, 256, 512, 512, C1h, C1l, 512LL * GN,
             nullptr, 0, 0, C2h, C2l, 256LL * GN,
             bc2, gc2, bb2, nullptr, nullptr, nullptr, 0, 1);

    // 8. out = Wc3@c2 + bc3
    run_gemm(Wc3h, Wc3l, 50, 256, 256, C2h, C2l, 256LL * GN,
             out, 50LL * GN, 0, nullptr, nullptr, 0,
             bc3, nullptr, nullptr, nullptr, nullptr, nullptr, 0, 0);
}